// round 1
// baseline (speedup 1.0000x reference)
#include <cuda_runtime.h>

#ifndef PI_F
#define PI_F 3.14159265358979323846f
#endif

__global__ void __launch_bounds__(256) helm_kernel(
    const float4* __restrict__ in4,   // [N/2] float4 = 2 rows each
    const float* __restrict__ a,      // [1]
    float2* __restrict__ out2,        // [N/2]
    int n4)                           // = N/2
{
    int i = blockIdx.x * blockDim.x + threadIdx.x;
    if (i >= n4) return;

    float av = a[0];
    float coef = av * av - 2.0f * PI_F * PI_F;

    float4 v = in4[i];
    float s0 = __sinf(PI_F * v.x) * __sinf(PI_F * v.y);
    float s1 = __sinf(PI_F * v.z) * __sinf(PI_F * v.w);

    out2[i] = make_float2(coef * s0, coef * s1);
}

extern "C" void kernel_launch(void* const* d_in, const int* in_sizes, int n_in,
                              void* d_out, int out_size) {
    const float* input = (const float*)d_in[0];   // [N, 2]
    const float* a     = (const float*)d_in[1];   // [1]
    float* out         = (float*)d_out;           // [N, 1]

    int n_rows = in_sizes[0] / 2;   // in_sizes[0] = N*2 elements
    int n4 = n_rows / 2;            // N is 16M, even

    int threads = 256;
    int blocks = (n4 + threads - 1) / threads;
    helm_kernel<<<blocks, threads>>>(
        (const float4*)input, a, (float2*)out, n4);
}

// round 2
// speedup vs baseline: 1.2062x; 1.2062x over previous
#include <cuda_runtime.h>

#ifndef PI_F
#define PI_F 3.14159265358979323846f
#endif

// Each thread: 4 independent float4 loads (2 rows each) -> 8 sin-products -> 4 float2 stores.
// Loads strided by blockDim so every LDG.128 is warp-contiguous; MLP_p1 = 4.
__global__ void __launch_bounds__(256) helm_kernel(
    const float4* __restrict__ in4,   // [n4] float4 = 2 rows each
    const float* __restrict__ a,      // [1]
    float2* __restrict__ out2,        // [n4]
    int n4)
{
    const int T = 256;
    int base = blockIdx.x * (T * 4) + threadIdx.x;

    float av = __ldg(a);
    float coef = av * av - 2.0f * PI_F * PI_F;

    int i0 = base;
    int i1 = base + T;
    int i2 = base + 2 * T;
    int i3 = base + 3 * T;

    if (i3 < n4) {
        // fast path: all 4 in-bounds, batch all loads up front
        float4 v0 = __ldcs(&in4[i0]);
        float4 v1 = __ldcs(&in4[i1]);
        float4 v2 = __ldcs(&in4[i2]);
        float4 v3 = __ldcs(&in4[i3]);

        float2 r0 = make_float2(coef * __sinf(PI_F * v0.x) * __sinf(PI_F * v0.y),
                                coef * __sinf(PI_F * v0.z) * __sinf(PI_F * v0.w));
        float2 r1 = make_float2(coef * __sinf(PI_F * v1.x) * __sinf(PI_F * v1.y),
                                coef * __sinf(PI_F * v1.z) * __sinf(PI_F * v1.w));
        float2 r2 = make_float2(coef * __sinf(PI_F * v2.x) * __sinf(PI_F * v2.y),
                                coef * __sinf(PI_F * v2.z) * __sinf(PI_F * v2.w));
        float2 r3 = make_float2(coef * __sinf(PI_F * v3.x) * __sinf(PI_F * v3.y),
                                coef * __sinf(PI_F * v3.z) * __sinf(PI_F * v3.w));

        __stcs(&out2[i0], r0);
        __stcs(&out2[i1], r1);
        __stcs(&out2[i2], r2);
        __stcs(&out2[i3], r3);
    } else {
        #pragma unroll
        for (int k = 0; k < 4; k++) {
            int i = base + k * T;
            if (i < n4) {
                float4 v = __ldcs(&in4[i]);
                float2 r = make_float2(coef * __sinf(PI_F * v.x) * __sinf(PI_F * v.y),
                                       coef * __sinf(PI_F * v.z) * __sinf(PI_F * v.w));
                __stcs(&out2[i], r);
            }
        }
    }
}

extern "C" void kernel_launch(void* const* d_in, const int* in_sizes, int n_in,
                              void* d_out, int out_size) {
    const float* input = (const float*)d_in[0];   // [N, 2]
    const float* a     = (const float*)d_in[1];   // [1]
    float* out         = (float*)d_out;           // [N, 1]

    int n_rows = in_sizes[0] / 2;   // N
    int n4 = n_rows / 2;            // float4 count (N even)

    int threads = 256;
    int per_block = threads * 4;
    int blocks = (n4 + per_block - 1) / per_block;
    helm_kernel<<<blocks, threads>>>(
        (const float4*)input, a, (float2*)out, n4);
}